// round 6
// baseline (speedup 1.0000x reference)
#include <cuda_runtime.h>
#include <cstdint>

#define M_DIM 4096
#define N_DIM 8192

// ---------------------------------------------------------------------------
// Single fused kernel.
// Grid: 128 blocks x 256 threads. Block b owns output rows [32b, 32b+32) x all
// 8192 cols.
// Phase 0: load MLP weights to smem; threads t<99 fold W5/b5 through
//          {Wc row0, Wc row1, bc} -> F[3][32], c3[3].
// Phase 1: MLP for 32 rows (8 warps x 4 interleaved chains), head reduction
//          -> sp[32][4] = (p0, p1, p2) per row.
// Phase 2: out[i][j] = p0*c0_j + p1*c1_j + p2, streamed STG.128.
// ---------------------------------------------------------------------------
__global__ __launch_bounds__(256) void fused_kernel(
    const float* __restrict__ noise,
    const float* __restrict__ coords,
    const float* __restrict__ W1, const float* __restrict__ b1,
    const float* __restrict__ W2, const float* __restrict__ b2,
    const float* __restrict__ W3, const float* __restrict__ b3,
    const float* __restrict__ W4, const float* __restrict__ b4,
    const float* __restrict__ W5, const float* __restrict__ b5,
    const float* __restrict__ Wc, const float* __restrict__ bc,
    const float* __restrict__ Wm, const float* __restrict__ bm,
    float* __restrict__ out)
{
    __shared__ float sW1[128 * 32];
    __shared__ float sW2[32 * 32];
    __shared__ float sW3[32 * 32];
    __shared__ float sW4[32 * 32];
    __shared__ float sb[4 * 32];
    __shared__ float sF[3][32];
    __shared__ float sc3[3];
    __shared__ float hbuf[32][33];
    __shared__ float sp[32][4];

    int tid  = threadIdx.x;
    int lane = tid & 31;
    int wid  = tid >> 5;

    // ---- Phase 0a: weights -> smem ----
    for (int i = tid; i < 128 * 32; i += 256) sW1[i] = W1[i];
    for (int i = tid; i < 32 * 32; i += 256) {
        sW2[i] = W2[i]; sW3[i] = W3[i]; sW4[i] = W4[i];
    }
    if (tid < 32) {
        sb[tid] = b1[tid]; sb[32 + tid] = b2[tid];
        sb[64 + tid] = b3[tid]; sb[96 + tid] = b4[tid];
    }

    // ---- Phase 0b: fold (redundant per block, tiny) ----
    // F[c][k] = sum_p W5[k*256+p] * G[c][p];  G = {Wc[0,:], Wc[1,:], bc}
    if (tid < 96) {
        int k = tid & 31, c = tid >> 5;
        const float* gr = (c == 0) ? Wc : (c == 1) ? (Wc + 256) : bc;
        const float* wr = W5 + k * 256;
        float s0 = 0.f, s1 = 0.f, s2 = 0.f, s3 = 0.f;
        #pragma unroll 16
        for (int p = 0; p < 256; p += 4) {
            s0 = fmaf(wr[p],     gr[p],     s0);
            s1 = fmaf(wr[p + 1], gr[p + 1], s1);
            s2 = fmaf(wr[p + 2], gr[p + 2], s2);
            s3 = fmaf(wr[p + 3], gr[p + 3], s3);
        }
        sF[c][k] = (s0 + s1) + (s2 + s3);
    } else if (tid < 99) {
        int c = tid - 96;
        const float* gr = (c == 0) ? Wc : (c == 1) ? (Wc + 256) : bc;
        float s0 = 0.f, s1 = 0.f, s2 = 0.f, s3 = 0.f;
        #pragma unroll 16
        for (int p = 0; p < 256; p += 4) {
            s0 = fmaf(b5[p],     gr[p],     s0);
            s1 = fmaf(b5[p + 1], gr[p + 1], s1);
            s2 = fmaf(b5[p + 2], gr[p + 2], s2);
            s3 = fmaf(b5[p + 3], gr[p + 3], s3);
        }
        float extra = (c == 0) ? Wm[0] : (c == 1) ? Wm[1] : bm[0];
        sc3[c] = ((s0 + s1) + (s2 + s3)) + extra;
    }
    __syncthreads();

    // ---- Phase 1: MLP, 4 interleaved row chains per warp ----
    int rows0 = blockIdx.x * 32;
    float x[4][4];   // [chain q][segment]
    #pragma unroll
    for (int q = 0; q < 4; q++) {
        const float* xr = noise + (rows0 + wid * 4 + q) * 128;
        x[q][0] = xr[lane];      x[q][1] = xr[lane + 32];
        x[q][2] = xr[lane + 64]; x[q][3] = xr[lane + 96];
    }

    float acc[4];
    #pragma unroll
    for (int q = 0; q < 4; q++) acc[q] = sb[lane];
    #pragma unroll
    for (int seg = 0; seg < 4; seg++) {
        #pragma unroll
        for (int k = 0; k < 32; k++) {
            float w = sW1[(seg * 32 + k) * 32 + lane];
            #pragma unroll
            for (int q = 0; q < 4; q++)
                acc[q] = fmaf(__shfl_sync(~0u, x[q][seg], k), w, acc[q]);
        }
    }
    float h[4];
    #pragma unroll
    for (int q = 0; q < 4; q++) h[q] = tanhf(acc[q]);

    #pragma unroll
    for (int L = 0; L < 3; L++) {
        const float* W = (L == 0) ? sW2 : (L == 1) ? sW3 : sW4;
        float nh[4];
        #pragma unroll
        for (int q = 0; q < 4; q++) nh[q] = sb[32 * (L + 1) + lane];
        #pragma unroll
        for (int k = 0; k < 32; k++) {
            float w = W[k * 32 + lane];
            #pragma unroll
            for (int q = 0; q < 4; q++)
                nh[q] = fmaf(__shfl_sync(~0u, h[q], k), w, nh[q]);
        }
        #pragma unroll
        for (int q = 0; q < 4; q++) h[q] = tanhf(nh[q]);
    }
    #pragma unroll
    for (int q = 0; q < 4; q++) hbuf[wid * 4 + q][lane] = h[q];
    __syncthreads();

    // head: p_c(row) = sum_k hbuf[row][k] * F[c][k] + c3[c]
    if (tid < 96) {
        int row = tid & 31, c = tid >> 5;
        float p0 = 0.f, p1 = 0.f;
        #pragma unroll
        for (int k = 0; k < 32; k += 2) {
            p0 = fmaf(hbuf[row][k],     sF[c][k],     p0);
            p1 = fmaf(hbuf[row][k + 1], sF[c][k + 1], p1);
        }
        sp[row][c] = (p0 + p1) + sc3[c];
    }
    __syncthreads();

    // ---- Phase 2: stream the 32 x 8192 slab ----
    float* oslab = out + (size_t)rows0 * N_DIM;
    #pragma unroll
    for (int chunk = 0; chunk < 8; chunk++) {
        int j = chunk * 1024 + tid * 4;
        float4 ca = *(const float4*)(coords + 2 * j);
        float4 cb = *(const float4*)(coords + 2 * j + 4);
        float* op = oslab + j;
        #pragma unroll 4
        for (int r = 0; r < 32; r++) {
            float p0 = sp[r][0], p1 = sp[r][1], p2 = sp[r][2];
            float4 v;
            v.x = fmaf(p0, ca.x, fmaf(p1, ca.y, p2));
            v.y = fmaf(p0, ca.z, fmaf(p1, ca.w, p2));
            v.z = fmaf(p0, cb.x, fmaf(p1, cb.y, p2));
            v.w = fmaf(p0, cb.z, fmaf(p1, cb.w, p2));
            *(float4*)(op + (size_t)r * N_DIM) = v;
        }
    }
}

// ---------------------------------------------------------------------------
extern "C" void kernel_launch(void* const* d_in, const int* in_sizes, int n_in,
                              void* d_out, int out_size) {
    const float* noise  = (const float*)d_in[0];
    const float* coords = (const float*)d_in[1];
    const float* W1 = (const float*)d_in[2];  const float* b1 = (const float*)d_in[3];
    const float* W2 = (const float*)d_in[4];  const float* b2 = (const float*)d_in[5];
    const float* W3 = (const float*)d_in[6];  const float* b3 = (const float*)d_in[7];
    const float* W4 = (const float*)d_in[8];  const float* b4 = (const float*)d_in[9];
    const float* W5 = (const float*)d_in[10]; const float* b5 = (const float*)d_in[11];
    const float* Wc = (const float*)d_in[12]; const float* bc = (const float*)d_in[13];
    const float* Wm = (const float*)d_in[14]; const float* bm = (const float*)d_in[15];
    float* out = (float*)d_out;

    fused_kernel<<<M_DIM / 32, 256>>>(noise, coords,
                                      W1, b1, W2, b2, W3, b3, W4, b4, W5, b5,
                                      Wc, bc, Wm, bm, out);
}